// round 2
// baseline (speedup 1.0000x reference)
#include <cuda_runtime.h>
#include <cstdint>

// Problem constants
#define BATCH   32
#define CH      512
#define HW      3136          // 56*56
#define NCL     27
#define NPAD    28
#define TOTPX   (BATCH * HW)              // 100352
#define PROBS_ELEMS (BATCH * NCL * HW)    // 2709504

// Scratch (no allocations allowed): normalized clusters transposed [CH][NPAD], loss accum
__device__ float  g_nct[CH * NPAD];
__device__ double g_accum;

// ---------- f32x2 packed helpers (sm_100+) ----------
__device__ __forceinline__ unsigned long long pack2(float lo, float hi) {
    unsigned long long r;
    asm("mov.b64 %0, {%1, %2};" : "=l"(r) : "f"(lo), "f"(hi));
    return r;
}
__device__ __forceinline__ void unpack2(unsigned long long v, float& lo, float& hi) {
    asm("mov.b64 {%0, %1}, %2;" : "=f"(lo), "=f"(hi) : "l"(v));
}
__device__ __forceinline__ unsigned long long fma2(unsigned long long a,
                                                   unsigned long long b,
                                                   unsigned long long c) {
    unsigned long long d;
    asm("fma.rn.f32x2 %0, %1, %2, %3;" : "=l"(d) : "l"(a), "l"(b), "l"(c));
    return d;
}

// ---------- Kernel A: normalize clusters into g_nct[c][n], zero accumulator ----------
// blockDim = 27 warps = 864 threads; warp w handles cluster row w.
__global__ void normalize_clusters_kernel(const float* __restrict__ clusters) {
    const int w = threadIdx.x >> 5;
    const int l = threadIdx.x & 31;
    if (threadIdx.x == 0) g_accum = 0.0;
    if (w == 0) {   // zero the pad column (n = 27)
        for (int c = l; c < CH; c += 32) g_nct[c * NPAD + NCL] = 0.0f;
    }
    if (w >= NCL) return;
    const float* row = clusters + (size_t)w * CH;
    float ss = 0.0f;
    for (int c = l; c < CH; c += 32) { float v = row[c]; ss += v * v; }
    #pragma unroll
    for (int o = 16; o > 0; o >>= 1) ss += __shfl_xor_sync(0xffffffffu, ss, o);
    const float inv = 1.0f / fmaxf(sqrtf(ss), 1e-12f);
    for (int c = l; c < CH; c += 32) g_nct[c * NPAD + w] = row[c] * inv;
}

// ---------- Kernel B: main fused kernel ----------
// 128 threads/block, 2 pixels/thread (one float2 / f32x2 pair). 392 blocks exact.
#define TPB     128
#define CCHUNK  128

template <bool OUT_ALIGNED>
__global__ void __launch_bounds__(TPB, 5)
cluster_main_kernel(const float* __restrict__ x, float* __restrict__ probs) {
    __shared__ float2 sclu[CCHUNK][NPAD];   // duplicated cluster values {v,v}
    __shared__ float  sred[TPB];

    const int tid = threadIdx.x;
    const int gp  = (blockIdx.x * TPB + tid) * 2;  // global pixel pair base
    const int b   = gp / HW;
    const int p   = gp - b * HW;
    const float* xb = x + (size_t)b * CH * HW + p;

    unsigned long long acc[NCL];
    #pragma unroll
    for (int n = 0; n < NCL; ++n) acc[n] = 0ull;
    unsigned long long ss = 0ull;

    for (int ch = 0; ch < CH / CCHUNK; ++ch) {
        __syncthreads();
        // stage 128 channels x 28 clusters as duplicated float2
        for (int idx = tid; idx < CCHUNK * NPAD; idx += TPB) {
            const int cc = idx / NPAD;
            const int n  = idx - cc * NPAD;
            const float v = g_nct[(ch * CCHUNK + cc) * NPAD + n];
            sclu[cc][n] = make_float2(v, v);
        }
        __syncthreads();

        const float* xc = xb + (size_t)(ch * CCHUNK) * HW;
        #pragma unroll 2
        for (int c = 0; c < CCHUNK; ++c) {
            const float2 xv = *(const float2*)(xc + (size_t)c * HW);
            const unsigned long long xp = pack2(xv.x, xv.y);
            ss = fma2(xp, xp, ss);
            #pragma unroll
            for (int n = 0; n < NCL; ++n) {
                const unsigned long long cv = *(const unsigned long long*)&sclu[c][n];
                acc[n] = fma2(xp, cv, acc[n]);
            }
        }
    }

    // ---------------- epilogue (2 pixels in registers) ----------------
    float ss0, ss1;
    unpack2(ss, ss0, ss1);
    const float inv0 = 1.0f / fmaxf(sqrtf(ss0), 1e-12f);
    const float inv1 = 1.0f / fmaxf(sqrtf(ss1), 1e-12f);

    float m0 = -1e30f, m1 = -1e30f;
    #pragma unroll
    for (int n = 0; n < NCL; ++n) {
        float a0, a1; unpack2(acc[n], a0, a1);
        a0 *= inv0; a1 *= inv1;
        m0 = fmaxf(m0, a0); m1 = fmaxf(m1, a1);
        acc[n] = pack2(a0, a1);                 // acc now holds cosine sims
    }
    float se0 = 0.f, se1 = 0.f, ses0 = 0.f, ses1 = 0.f;
    #pragma unroll
    for (int n = 0; n < NCL; ++n) {
        float s0, s1; unpack2(acc[n], s0, s1);
        const float e0 = __expf(2.0f * (s0 - m0));
        const float e1 = __expf(2.0f * (s1 - m1));
        se0 += e0; se1 += e1;
        ses0 += e0 * s0; ses1 += e1 * s1;
        acc[n] = pack2(e0, e1);                 // acc now holds exps
    }
    const float r0 = 1.0f / se0;
    const float r1 = 1.0f / se1;

    if (probs != nullptr) {
        float* op = probs + (size_t)b * NCL * HW + p;
        #pragma unroll
        for (int n = 0; n < NCL; ++n) {
            float e0, e1; unpack2(acc[n], e0, e1);
            if (OUT_ALIGNED) {
                *(float2*)(op + (size_t)n * HW) = make_float2(e0 * r0, e1 * r1);
            } else {
                op[(size_t)n * HW]     = e0 * r0;
                op[(size_t)n * HW + 1] = e1 * r1;
            }
        }
    }

    // loss contribution: sum_n p_n * s_n per pixel
    sred[tid] = ses0 * r0 + ses1 * r1;
    __syncthreads();
    #pragma unroll
    for (int s = TPB / 2; s > 0; s >>= 1) {
        if (tid < s) sred[tid] += sred[tid + s];
        __syncthreads();
    }
    if (tid == 0) atomicAdd(&g_accum, (double)sred[0]);
}

// ---------- Kernel C: finalize loss ----------
__global__ void finalize_kernel(float* __restrict__ loss) {
    *loss = (float)(-g_accum / (double)TOTPX);
}

extern "C" void kernel_launch(void* const* d_in, const int* in_sizes, int n_in,
                              void* d_out, int out_size) {
    const float* x        = (const float*)d_in[0];
    const float* clusters = (const float*)d_in[1];
    float* out = (float*)d_out;

    float* probs_ptr = nullptr;
    float* loss_ptr  = nullptr;
    if (out_size >= PROBS_ELEMS) {
        probs_ptr = out + (out_size - PROBS_ELEMS);   // loss (if any) precedes probs
        if (out_size > PROBS_ELEMS) loss_ptr = out;
    } else {
        loss_ptr = out;                               // loss-only output
    }

    normalize_clusters_kernel<<<1, NCL * 32>>>(clusters);

    const bool aligned = (((uintptr_t)probs_ptr & 7) == 0);
    if (aligned) {
        cluster_main_kernel<true ><<<TOTPX / (2 * TPB), TPB>>>(x, probs_ptr);
    } else {
        cluster_main_kernel<false><<<TOTPX / (2 * TPB), TPB>>>(x, probs_ptr);
    }
    if (loss_ptr) finalize_kernel<<<1, 1>>>(loss_ptr);
}

// round 4
// speedup vs baseline: 1.5994x; 1.5994x over previous
#include <cuda_runtime.h>
#include <cstdint>

// ---------------- problem constants ----------------
#define BATCH   32
#define CH      512
#define HW      3136
#define NCL     27
#define NPAD    28
#define TOTPX   (BATCH * HW)
#define PROBS_ELEMS (BATCH * NCL * HW)

#define PXT     224                 // pixels per CTA (224 | 3136)
#define TPB     224                 // threads per CTA
#define GRP     56                  // pixel groups (4 px each)
#define NSUB    4                   // cluster subsets (7 clusters each, n=27 pad)
#define CPS     7                   // clusters per subset
#define CCH     8                   // channels per chunk
#define NCHUNKS (CH / CCH)          // 64
#define TILES_PER_B (HW / PXT)      // 14

typedef unsigned long long ull;

// ---------------- device scratch ----------------
__device__ float  g_nct[CH * NPAD];   // normalized clusters transposed [c][n], n=27 zero
__device__ double g_accum;

// ---------------- f32x2 helpers ----------------
__device__ __forceinline__ ull fma2(ull a, ull b, ull c) {
    ull d;
    asm("fma.rn.f32x2 %0, %1, %2, %3;" : "=l"(d) : "l"(a), "l"(b), "l"(c));
    return d;
}
__device__ __forceinline__ void unpack2(ull v, float& lo, float& hi) {
    asm("mov.b64 {%0, %1}, %2;" : "=f"(lo), "=f"(hi) : "l"(v));
}

// ---------------- Kernel A: normalize clusters (28 blocks x 256) ----------------
__global__ void normalize_clusters(const float* __restrict__ clusters) {
    __shared__ float swarp[8];
    const int n = blockIdx.x;
    const int tid = threadIdx.x, lane = tid & 31, w = tid >> 5;
    if (n >= NCL) {           // pad block: zero col n=27, reset accumulator
        for (int c = tid; c < CH; c += 256) g_nct[c * NPAD + NCL] = 0.0f;
        if (tid == 0) g_accum = 0.0;
        return;
    }
    const float* row = clusters + (size_t)n * CH;
    float ss = 0.0f;
    for (int c = tid; c < CH; c += 256) { float v = row[c]; ss += v * v; }
    #pragma unroll
    for (int o = 16; o > 0; o >>= 1) ss += __shfl_xor_sync(0xffffffffu, ss, o);
    if (lane == 0) swarp[w] = ss;
    __syncthreads();
    if (tid == 0) {
        float t = 0.0f;
        #pragma unroll
        for (int i = 0; i < 8; ++i) t += swarp[i];
        swarp[0] = t;
    }
    __syncthreads();
    const float inv = 1.0f / fmaxf(sqrtf(swarp[0]), 1e-12f);
    for (int c = tid; c < CH; c += 256) g_nct[c * NPAD + n] = row[c] * inv;
}

// ---------------- Kernel B: main fused kernel ----------------
// SMEM plan (union):
//   mainloop: xs double buf  2 * (CCH*PXT*4)  = 14336 B  at offset 0
//             sclu double buf 2 * (CCH*NPAD*8) = 3584 B  at offset 14336
//   epilogue: ssim [NPAD][PXT] floats = 25088 B at offset 0
//             sss  [PXT] floats       =   896 B at offset 25088
#define XS_BYTES    (CCH * PXT * 4)           // 7168
#define SCLU_OFF    (2 * XS_BYTES)            // 14336
#define SCLU_BYTES  (CCH * NPAD * 8)          // 1792
#define SSS_OFF     (NPAD * PXT * 4)          // 25088
#define SMEM_BYTES  (SSS_OFF + PXT * 4 + 64)  // ~26 KB

__global__ void __launch_bounds__(TPB, 3)
cluster_main(const float* __restrict__ x, float* __restrict__ probs) {
    __shared__ __align__(16) char sm[SMEM_BYTES];
    __shared__ float sred[8];

    const int tid  = threadIdx.x;
    const int lane = tid & 31;
    const int warp = tid >> 5;
    const int b    = blockIdx.x / TILES_PER_B;
    const int tile = blockIdx.x % TILES_PER_B;
    const int g    = tid % GRP;         // pixel group (4 px)
    const int s    = tid / GRP;         // cluster subset
    const int nb   = s * CPS;           // first cluster of subset

    const float* xtile = x + (size_t)b * CH * HW + tile * PXT;

    // ---- staging lambdas ----
    auto stage = [&](int chunk, int buf) {
        const float* src = xtile + (size_t)chunk * CCH * HW;
        float2* xs = (float2*)(sm + buf * XS_BYTES);
        #pragma unroll
        for (int i = 0; i < 4; ++i) {
            const int idx = tid + TPB * i;        // 0..895
            const int ch  = idx / 112;            // 112 float2 per channel row
            const int pr  = idx - ch * 112;
            xs[ch * 112 + pr] = *(const float2*)(src + (size_t)ch * HW + pr * 2);
        }
        const float v = g_nct[chunk * CCH * NPAD + tid];   // contiguous 224 floats
        ((float2*)(sm + SCLU_OFF + buf * SCLU_BYTES))[tid] = make_float2(v, v);
    };

    ull a0[CPS], a1[CPS];
    #pragma unroll
    for (int i = 0; i < CPS; ++i) { a0[i] = 0ull; a1[i] = 0ull; }
    ull ss0 = 0ull, ss1 = 0ull;

    stage(0, 0);
    for (int chunk = 0; chunk < NCHUNKS; ++chunk) {
        __syncthreads();
        if (chunk + 1 < NCHUNKS) stage(chunk + 1, (chunk + 1) & 1);

        const float2* xs  = (const float2*)(sm + (chunk & 1) * XS_BYTES);
        const ull*    scl = (const ull*)(sm + SCLU_OFF + (chunk & 1) * SCLU_BYTES);
        #pragma unroll
        for (int c = 0; c < CCH; ++c) {
            const ull xp0 = *(const ull*)&xs[c * 112 + g * 2];
            const ull xp1 = *(const ull*)&xs[c * 112 + g * 2 + 1];
            if (s == 0) { ss0 = fma2(xp0, xp0, ss0); ss1 = fma2(xp1, xp1, ss1); }
            #pragma unroll
            for (int i = 0; i < CPS; ++i) {
                const ull cv = scl[c * NPAD + nb + i];
                a0[i] = fma2(xp0, cv, a0[i]);
                a1[i] = fma2(xp1, cv, a1[i]);
            }
        }
    }

    // ---- spill sims + ss to smem, remap thread=pixel ----
    __syncthreads();   // mainloop smem dead; reuse as ssim
    float* ssim = (float*)sm;                       // [NPAD][PXT]
    float* sss  = (float*)(sm + SSS_OFF);           // [PXT]
    #pragma unroll
    for (int i = 0; i < CPS; ++i) {
        float v0, v1, v2, v3;
        unpack2(a0[i], v0, v1);
        unpack2(a1[i], v2, v3);
        float* r = ssim + (nb + i) * PXT + g * 4;
        r[0] = v0; r[1] = v1; r[2] = v2; r[3] = v3;
    }
    if (s == 0) {
        float q0, q1, q2, q3;
        unpack2(ss0, q0, q1);
        unpack2(ss1, q2, q3);
        float* r = sss + g * 4;
        r[0] = q0; r[1] = q1; r[2] = q2; r[3] = q3;
    }
    __syncthreads();

    // ---- per-pixel softmax (thread t = pixel t) ----
    const float inv = 1.0f / fmaxf(sqrtf(sss[tid]), 1e-12f);
    float sims[NCL], m = -1e30f;
    #pragma unroll
    for (int n = 0; n < NCL; ++n) {
        sims[n] = ssim[n * PXT + tid] * inv;
        m = fmaxf(m, sims[n]);
    }
    float se = 0.0f, ses = 0.0f;
    #pragma unroll
    for (int n = 0; n < NCL; ++n) {
        const float e = __expf(2.0f * (sims[n] - m));
        se += e; ses += e * sims[n];
        sims[n] = e;
    }
    const float r = 1.0f / se;

    if (probs != nullptr) {
        float* op = probs + (size_t)b * NCL * HW + tile * PXT + tid;
        #pragma unroll
        for (int n = 0; n < NCL; ++n) op[(size_t)n * HW] = sims[n] * r;
    }

    // ---- loss reduction ----
    float c = ses * r;
    #pragma unroll
    for (int o = 16; o > 0; o >>= 1) c += __shfl_xor_sync(0xffffffffu, c, o);
    if (lane == 0) sred[warp] = c;
    __syncthreads();
    if (tid == 0) {
        float t = 0.0f;
        #pragma unroll
        for (int i = 0; i < 7; ++i) t += sred[i];
        atomicAdd(&g_accum, (double)t);
    }
}

// ---------------- Kernel C: finalize ----------------
__global__ void finalize_kernel(float* __restrict__ loss) {
    *loss = (float)(-g_accum / (double)TOTPX);
}

extern "C" void kernel_launch(void* const* d_in, const int* in_sizes, int n_in,
                              void* d_out, int out_size) {
    const float* x        = (const float*)d_in[0];
    const float* clusters = (const float*)d_in[1];
    float* out = (float*)d_out;

    float* probs_ptr = nullptr;
    float* loss_ptr  = nullptr;
    if (out_size >= PROBS_ELEMS) {
        probs_ptr = out + (out_size - PROBS_ELEMS);
        if (out_size > PROBS_ELEMS) loss_ptr = out;
    } else {
        loss_ptr = out;
    }

    normalize_clusters<<<NPAD, 256>>>(clusters);
    cluster_main<<<BATCH * TILES_PER_B, TPB>>>(x, probs_ptr);
    if (loss_ptr) finalize_kernel<<<1, 1>>>(loss_ptr);
}

// round 6
// speedup vs baseline: 1.7498x; 1.0940x over previous
#include <cuda_runtime.h>
#include <cstdint>

// ---------------- problem constants ----------------
#define BATCH   32
#define CH      512
#define HW      3136
#define NCL     27
#define TOTPX   (BATCH * HW)
#define PROBS_ELEMS (BATCH * NCL * HW)

#define MTILE   128                 // pixels per CTA
#define TILES_PER_B 25              // ceil(3136/128), last tile 64 valid
#define TPB     128
#define CCH     8                   // channels per chunk (K step granule)
#define NCHUNKS (CH / CCH)          // 64
#define NPADN   32                  // clusters padded to 32 (rows 27-31 zero)

// ---------------- smem layout (union) ----------------
#define XS_STRIDE 136               // floats; conflict-free for A frag loads
#define XS_PLANE  (CCH * XS_STRIDE)             // floats per plane (hi or lo)
#define XS_BYTES  (2 * XS_PLANE * 4)            // 8704 per buffer (hi+lo)
#define SB_OFF    (2 * XS_BYTES)                // 17408
#define SB_STRIDE 12                // floats; conflict-free for B frag loads
#define SB_PLANE  (NPADN * SB_STRIDE)           // floats per plane
#define SB_BYTES  (2 * SB_PLANE * 4)            // 3072 per buffer (hi+lo)
#define SSIM_STRIDE 132             // epilogue [32][132]
#define MAINLOOP_BYTES (SB_OFF + 2 * SB_BYTES)  // 23552
#define SMEM_BYTES  MAINLOOP_BYTES              // > 16896 epilogue need

// ---------------- device scratch ----------------
__device__ float  g_ncl[NPADN * CH];   // normalized clusters [32][512], rows 27-31 zero
__device__ double g_accum;

// ---------------- tf32 helpers ----------------
__device__ __forceinline__ float tf32_rna(float x) {
    uint32_t u;
    asm("cvt.rna.tf32.f32 %0, %1;" : "=r"(u) : "f"(x));
    return __uint_as_float(u);
}
__device__ __forceinline__ void mma_tf32(float* d, const uint32_t* a, const uint32_t* b) {
    asm volatile(
        "mma.sync.aligned.m16n8k8.row.col.f32.tf32.tf32.f32 "
        "{%0,%1,%2,%3}, {%4,%5,%6,%7}, {%8,%9}, {%0,%1,%2,%3};"
        : "+f"(d[0]), "+f"(d[1]), "+f"(d[2]), "+f"(d[3])
        : "r"(a[0]), "r"(a[1]), "r"(a[2]), "r"(a[3]), "r"(b[0]), "r"(b[1]));
}

// ---------------- Kernel A: normalize clusters (28 blocks x 256) ----------------
__global__ void normalize_clusters(const float* __restrict__ clusters) {
    __shared__ float swarp[8];
    const int n = blockIdx.x;
    const int tid = threadIdx.x, lane = tid & 31, w = tid >> 5;
    if (n >= NCL) {       // pad block: zero rows 27-31, reset accumulator
        for (int i = tid; i < (NPADN - NCL) * CH; i += 256) g_ncl[NCL * CH + i] = 0.0f;
        if (tid == 0) g_accum = 0.0;
        return;
    }
    const float* row = clusters + (size_t)n * CH;
    float ss = 0.0f;
    for (int c = tid; c < CH; c += 256) { float v = row[c]; ss += v * v; }
    #pragma unroll
    for (int o = 16; o > 0; o >>= 1) ss += __shfl_xor_sync(0xffffffffu, ss, o);
    if (lane == 0) swarp[w] = ss;
    __syncthreads();
    if (tid == 0) {
        float t = 0.0f;
        #pragma unroll
        for (int i = 0; i < 8; ++i) t += swarp[i];
        swarp[0] = t;
    }
    __syncthreads();
    const float inv = 1.0f / fmaxf(sqrtf(swarp[0]), 1e-12f);
    for (int c = tid; c < CH; c += 256) g_ncl[n * CH + c] = row[c] * inv;
}

// ---------------- Kernel B: main tf32x3-HMMA fused kernel ----------------
__global__ void __launch_bounds__(TPB, 4)
cluster_main(const float* __restrict__ x, float* __restrict__ probs) {
    __shared__ __align__(16) char sm[SMEM_BYTES];
    __shared__ float sred[4];

    const int tid  = threadIdx.x;
    const int lane = tid & 31;
    const int warp = tid >> 5;
    const int b    = blockIdx.x / TILES_PER_B;
    const int tile = blockIdx.x % TILES_PER_B;
    const int pix  = tile * MTILE + tid;
    const bool valid = (pix < HW);
    const float* xcol = x + (size_t)b * CH * HW + (valid ? pix : (HW - 1));

    const int bn = tid >> 2;                 // B staging: cluster row 0..31
    const int bk = (tid & 3) * 2;            // two k per thread

    float v[CCH];
    float bv0, bv1;
    float ss = 0.0f;

    auto load_regs = [&](int kc) {
        const float* src = xcol + (size_t)kc * CCH * HW;
        #pragma unroll
        for (int c = 0; c < CCH; ++c) v[c] = src[(size_t)c * HW];
        const float* gb = g_ncl + bn * CH + kc * CCH + bk;
        bv0 = gb[0]; bv1 = gb[1];
    };
    auto store_smem = [&](int buf) {
        float* xs_hi = (float*)(sm + buf * XS_BYTES);
        float* xs_lo = xs_hi + XS_PLANE;
        #pragma unroll
        for (int c = 0; c < CCH; ++c) {
            const float hi = tf32_rna(v[c]);
            xs_hi[c * XS_STRIDE + tid] = hi;
            xs_lo[c * XS_STRIDE + tid] = v[c] - hi;
            ss = fmaf(v[c], v[c], ss);
        }
        float* sB_hi = (float*)(sm + SB_OFF + buf * SB_BYTES);
        float* sB_lo = sB_hi + SB_PLANE;
        const float h0 = tf32_rna(bv0), h1 = tf32_rna(bv1);
        sB_hi[bn * SB_STRIDE + bk]     = h0;
        sB_hi[bn * SB_STRIDE + bk + 1] = h1;
        sB_lo[bn * SB_STRIDE + bk]     = bv0 - h0;
        sB_lo[bn * SB_STRIDE + bk + 1] = bv1 - h1;
    };

    float d[2][4][4];
    #pragma unroll
    for (int mt = 0; mt < 2; ++mt)
        #pragma unroll
        for (int nt = 0; nt < 4; ++nt)
            #pragma unroll
            for (int i = 0; i < 4; ++i) d[mt][nt][i] = 0.0f;

    const int wpx = warp * 32;               // warp's pixel base (M rows)

    load_regs(0);
    store_smem(0);
    for (int kc = 0; kc < NCHUNKS; ++kc) {
        __syncthreads();
        const bool has_next = (kc + 1 < NCHUNKS);
        if (has_next) load_regs(kc + 1);

        const float* xs_hi = (const float*)(sm + (kc & 1) * XS_BYTES);
        const float* xs_lo = xs_hi + XS_PLANE;
        const float* sB_hi = (const float*)(sm + SB_OFF + (kc & 1) * SB_BYTES);
        const float* sB_lo = sB_hi + SB_PLANE;

        uint32_t ah[2][4], al[2][4], bh[4][2], bl[4][2];
        #pragma unroll
        for (int mt = 0; mt < 2; ++mt) {
            const int base = (lane & 3) * XS_STRIDE + wpx + mt * 16 + (lane >> 2);
            ah[mt][0] = __float_as_uint(xs_hi[base]);
            ah[mt][1] = __float_as_uint(xs_hi[base + 8]);
            ah[mt][2] = __float_as_uint(xs_hi[base + 4 * XS_STRIDE]);
            ah[mt][3] = __float_as_uint(xs_hi[base + 4 * XS_STRIDE + 8]);
            al[mt][0] = __float_as_uint(xs_lo[base]);
            al[mt][1] = __float_as_uint(xs_lo[base + 8]);
            al[mt][2] = __float_as_uint(xs_lo[base + 4 * XS_STRIDE]);
            al[mt][3] = __float_as_uint(xs_lo[base + 4 * XS_STRIDE + 8]);
        }
        #pragma unroll
        for (int nt = 0; nt < 4; ++nt) {
            const int bb = (nt * 8 + (lane >> 2)) * SB_STRIDE + (lane & 3);
            bh[nt][0] = __float_as_uint(sB_hi[bb]);
            bh[nt][1] = __float_as_uint(sB_hi[bb + 4]);
            bl[nt][0] = __float_as_uint(sB_lo[bb]);
            bl[nt][1] = __float_as_uint(sB_lo[bb + 4]);
        }
        #pragma unroll
        for (int mt = 0; mt < 2; ++mt)
            #pragma unroll
            for (int nt = 0; nt < 4; ++nt) {
                mma_tf32(d[mt][nt], ah[mt], bl[nt]);   // hi*lo
                mma_tf32(d[mt][nt], al[mt], bh[nt]);   // lo*hi
                mma_tf32(d[mt][nt], ah[mt], bh[nt]);   // hi*hi (largest last)
            }

        if (has_next) store_smem((kc + 1) & 1);
    }

    // ---- epilogue: frags -> smem, remap thread = pixel ----
    __syncthreads();
    float* ssim = (float*)sm;                // [32][SSIM_STRIDE]
    #pragma unroll
    for (int mt = 0; mt < 2; ++mt) {
        const int r0 = wpx + mt * 16 + (lane >> 2);
        #pragma unroll
        for (int nt = 0; nt < 4; ++nt) {
            const int n0 = nt * 8 + (lane & 3) * 2;
            ssim[n0 * SSIM_STRIDE + r0]           = d[mt][nt][0];
            ssim[(n0 + 1) * SSIM_STRIDE + r0]     = d[mt][nt][1];
            ssim[n0 * SSIM_STRIDE + r0 + 8]       = d[mt][nt][2];
            ssim[(n0 + 1) * SSIM_STRIDE + r0 + 8] = d[mt][nt][3];
        }
    }
    __syncthreads();

    const float inv = 1.0f / fmaxf(sqrtf(ss), 1e-12f);
    float sims[NCL], m = -1e30f;
    #pragma unroll
    for (int n = 0; n < NCL; ++n) {
        sims[n] = ssim[n * SSIM_STRIDE + tid] * inv;
        m = fmaxf(m, sims[n]);
    }
    float se = 0.0f, ses = 0.0f;
    #pragma unroll
    for (int n = 0; n < NCL; ++n) {
        const float e = __expf(2.0f * (sims[n] - m));
        se += e; ses += e * sims[n];
        sims[n] = e;
    }
    const float r = 1.0f / se;

    if (probs != nullptr && valid) {
        float* op = probs + (size_t)b * NCL * HW + pix;
        #pragma unroll
        for (int n = 0; n < NCL; ++n) op[(size_t)n * HW] = sims[n] * r;
    }

    // ---- loss reduction ----
    float c = valid ? (ses * r) : 0.0f;
    #pragma unroll
    for (int o = 16; o > 0; o >>= 1) c += __shfl_xor_sync(0xffffffffu, c, o);
    if (lane == 0) sred[warp] = c;
    __syncthreads();
    if (tid == 0)
        atomicAdd(&g_accum, (double)(sred[0] + sred[1] + sred[2] + sred[3]));
}

// ---------------- Kernel C: finalize ----------------
__global__ void finalize_kernel(float* __restrict__ loss) {
    *loss = (float)(-g_accum / (double)TOTPX);
}

extern "C" void kernel_launch(void* const* d_in, const int* in_sizes, int n_in,
                              void* d_out, int out_size) {
    const float* x        = (const float*)d_in[0];
    const float* clusters = (const float*)d_in[1];
    float* out = (float*)d_out;

    float* probs_ptr = nullptr;
    float* loss_ptr  = nullptr;
    if (out_size >= PROBS_ELEMS) {
        probs_ptr = out + (out_size - PROBS_ELEMS);
        if (out_size > PROBS_ELEMS) loss_ptr = out;
    } else {
        loss_ptr = out;
    }

    normalize_clusters<<<NCL + 1, 256>>>(clusters);
    cluster_main<<<BATCH * TILES_PER_B, TPB>>>(x, probs_ptr);
    if (loss_ptr) finalize_kernel<<<1, 1>>>(loss_ptr);
}

// round 7
// speedup vs baseline: 2.6693x; 1.5255x over previous
#include <cuda_runtime.h>
#include <cstdint>

// ---------------- problem constants ----------------
#define BATCH   32
#define CH      512
#define HW      3136
#define NCL     27
#define TOTPX   (BATCH * HW)
#define PROBS_ELEMS (BATCH * NCL * HW)

#define MTILE   128                 // pixels per CTA
#define TILES_PER_B 25              // ceil(3136/128), last tile 64 valid
#define TPB     128
#define CCH     8                   // channels per chunk (K step)
#define NCHUNKS (CH / CCH)          // 64
#define NPADN   32                  // clusters padded to 32 (rows 27-31 zero)

// ---------------- smem: 5-stage cp.async ring ----------------
#define XS_STRIDE  136                              // floats, conflict-free frags
#define XSTG_BYTES (CCH * XS_STRIDE * 4)            // 4352 (x raw)
#define SB_STRIDE  12
#define BPLANE     (NPADN * SB_STRIDE * 4)          // 1536
#define BSTG_BYTES (2 * BPLANE)                     // 3072 (B hi+lo)
#define STG_BYTES  (XSTG_BYTES + BSTG_BYTES)        // 7424
#define STAGES     5
#define SMEM_BYTES (STAGES * STG_BYTES)             // 37120
#define SSIM_STRIDE 132
#define SSS_OFF    (NPADN * SSIM_STRIDE * 4)        // 16896 (epilogue union)

// ---------------- device scratch ----------------
__device__ float  g_nsplit[2 * NPADN * CH];  // [hi|lo][32][512], pad rows zero
__device__ double g_accum;

// ---------------- helpers ----------------
__device__ __forceinline__ float tf32_rna(float x) {
    uint32_t u;
    asm("cvt.rna.tf32.f32 %0, %1;" : "=r"(u) : "f"(x));
    return __uint_as_float(u);
}
__device__ __forceinline__ void mma_tf32(float* d, const uint32_t* a, const uint32_t* b) {
    asm volatile(
        "mma.sync.aligned.m16n8k8.row.col.f32.tf32.tf32.f32 "
        "{%0,%1,%2,%3}, {%4,%5,%6,%7}, {%8,%9}, {%0,%1,%2,%3};"
        : "+f"(d[0]), "+f"(d[1]), "+f"(d[2]), "+f"(d[3])
        : "r"(a[0]), "r"(a[1]), "r"(a[2]), "r"(a[3]), "r"(b[0]), "r"(b[1]));
}
__device__ __forceinline__ void cp16(uint32_t dst, const void* src, int nbytes) {
    asm volatile("cp.async.cg.shared.global [%0], [%1], 16, %2;"
                 :: "r"(dst), "l"(src), "r"(nbytes) : "memory");
}
#define CP_COMMIT()  asm volatile("cp.async.commit_group;" ::: "memory")
#define CP_WAIT3()   asm volatile("cp.async.wait_group 3;" ::: "memory")

// ---------------- Kernel A: normalize clusters + hi/lo split ----------------
__global__ void normalize_clusters(const float* __restrict__ clusters) {
    __shared__ float swarp[8];
    const int n = blockIdx.x;
    const int tid = threadIdx.x, lane = tid & 31, w = tid >> 5;
    if (n >= NCL) {       // pad block: zero rows 27-31 both planes, reset accum
        for (int i = tid; i < (NPADN - NCL) * CH; i += 256) {
            g_nsplit[NCL * CH + i] = 0.0f;
            g_nsplit[NPADN * CH + NCL * CH + i] = 0.0f;
        }
        if (tid == 0) g_accum = 0.0;
        return;
    }
    const float* row = clusters + (size_t)n * CH;
    float ss = 0.0f;
    for (int c = tid; c < CH; c += 256) { float v = row[c]; ss += v * v; }
    #pragma unroll
    for (int o = 16; o > 0; o >>= 1) ss += __shfl_xor_sync(0xffffffffu, ss, o);
    if (lane == 0) swarp[w] = ss;
    __syncthreads();
    if (tid == 0) {
        float t = 0.0f;
        #pragma unroll
        for (int i = 0; i < 8; ++i) t += swarp[i];
        swarp[0] = t;
    }
    __syncthreads();
    const float inv = 1.0f / fmaxf(sqrtf(swarp[0]), 1e-12f);
    for (int c = tid; c < CH; c += 256) {
        const float v  = row[c] * inv;
        const float hi = tf32_rna(v);
        g_nsplit[n * CH + c]              = hi;
        g_nsplit[NPADN * CH + n * CH + c] = v - hi;
    }
}

// ---------------- Kernel B: main tf32x3 HMMA, cp.async pipelined ----------------
__global__ void __launch_bounds__(TPB, 4)
cluster_main(const float* __restrict__ x, float* __restrict__ probs) {
    __shared__ __align__(16) char sm[SMEM_BYTES];
    __shared__ float sred[4];

    const int tid  = threadIdx.x;
    const int lane = tid & 31;
    const int warp = tid >> 5;
    const int b    = blockIdx.x / TILES_PER_B;
    const int tile = blockIdx.x % TILES_PER_B;
    const int pix  = tile * MTILE + tid;
    const bool valid = (pix < HW);

    const float* xtile = x + (size_t)b * CH * HW + tile * MTILE;
    const uint32_t smb = (uint32_t)__cvta_generic_to_shared(sm);

    // x validity for this thread's cp.async segment (4 px, HW % 4 == 0)
    const int seg_px = tile * MTILE + lane * 4;
    const bool seg_ok = (seg_px + 4 <= HW);
    const int xbytes = seg_ok ? 16 : 0;

    // B staging assignment: 1x 16B per thread
    const int bplane = tid >> 6;            // 0 = hi, 1 = lo
    const int bt     = tid & 63;
    const int brow   = bt >> 1;
    const int bhalf  = bt & 1;
    const float* bsrc_base = g_nsplit + (size_t)(bplane * NPADN + brow) * CH + bhalf * 4;

    auto issue_stage = [&](int chunk) {
        const uint32_t base = smb + (uint32_t)(chunk % STAGES) * STG_BYTES;
        // x: 2 transfers, channels warp and warp+4
        const float* s0 = xtile + (size_t)(chunk * CCH + warp) * HW + lane * 4;
        const float* s1 = s0 + (size_t)4 * HW;
        cp16(base + (uint32_t)warp * (XS_STRIDE * 4) + lane * 16,
             seg_ok ? (const void*)s0 : (const void*)xtile, xbytes);
        cp16(base + (uint32_t)(warp + 4) * (XS_STRIDE * 4) + lane * 16,
             seg_ok ? (const void*)s1 : (const void*)xtile, xbytes);
        // B: 1 transfer
        cp16(base + XSTG_BYTES + (uint32_t)bplane * BPLANE + brow * (SB_STRIDE * 4) + bhalf * 16,
             bsrc_base + chunk * CCH, 16);
    };

    float d[2][4][4];
    #pragma unroll
    for (int mt = 0; mt < 2; ++mt)
        #pragma unroll
        for (int nt = 0; nt < 4; ++nt)
            #pragma unroll
            for (int i = 0; i < 4; ++i) d[mt][nt][i] = 0.0f;
    float ssr[2][2] = {{0.f, 0.f}, {0.f, 0.f}};

    const int wpx = warp * 32;

    issue_stage(0); CP_COMMIT();
    issue_stage(1); CP_COMMIT();
    issue_stage(2); CP_COMMIT();

    for (int kc = 0; kc < NCHUNKS; ++kc) {
        if (kc + 3 < NCHUNKS) issue_stage(kc + 3);
        CP_COMMIT();
        CP_WAIT3();
        __syncthreads();

        const char* stg  = sm + (kc % STAGES) * STG_BYTES;
        const float* xs  = (const float*)stg;
        const float* sBh = (const float*)(stg + XSTG_BYTES);
        const float* sBl = (const float*)(stg + XSTG_BYTES + BPLANE);

        uint32_t ah[2][4], al[2][4], bh[4][2], bl[4][2];
        #pragma unroll
        for (int mt = 0; mt < 2; ++mt) {
            const int base = (lane & 3) * XS_STRIDE + wpx + mt * 16 + (lane >> 2);
            const float r0 = xs[base];
            const float r1 = xs[base + 8];
            const float r2 = xs[base + 4 * XS_STRIDE];
            const float r3 = xs[base + 4 * XS_STRIDE + 8];
            ssr[mt][0] = fmaf(r0, r0, fmaf(r2, r2, ssr[mt][0]));
            ssr[mt][1] = fmaf(r1, r1, fmaf(r3, r3, ssr[mt][1]));
            const float h0 = tf32_rna(r0), h1 = tf32_rna(r1);
            const float h2 = tf32_rna(r2), h3 = tf32_rna(r3);
            ah[mt][0] = __float_as_uint(h0); al[mt][0] = __float_as_uint(r0 - h0);
            ah[mt][1] = __float_as_uint(h1); al[mt][1] = __float_as_uint(r1 - h1);
            ah[mt][2] = __float_as_uint(h2); al[mt][2] = __float_as_uint(r2 - h2);
            ah[mt][3] = __float_as_uint(h3); al[mt][3] = __float_as_uint(r3 - h3);
        }
        #pragma unroll
        for (int nt = 0; nt < 4; ++nt) {
            const int bb = (nt * 8 + (lane >> 2)) * SB_STRIDE + (lane & 3);
            bh[nt][0] = __float_as_uint(sBh[bb]);
            bh[nt][1] = __float_as_uint(sBh[bb + 4]);
            bl[nt][0] = __float_as_uint(sBl[bb]);
            bl[nt][1] = __float_as_uint(sBl[bb + 4]);
        }
        #pragma unroll
        for (int mt = 0; mt < 2; ++mt)
            #pragma unroll
            for (int nt = 0; nt < 4; ++nt) {
                mma_tf32(d[mt][nt], ah[mt], bl[nt]);   // hi*lo
                mma_tf32(d[mt][nt], al[mt], bh[nt]);   // lo*hi
                mma_tf32(d[mt][nt], ah[mt], bh[nt]);   // hi*hi
            }
        __syncthreads();
    }

    // ---- epilogue: frags + row norms -> smem, remap thread = pixel ----
    float* ssim = (float*)sm;                 // [32][SSIM_STRIDE]
    float* sss  = (float*)(sm + SSS_OFF);     // [128]
    #pragma unroll
    for (int mt = 0; mt < 2; ++mt) {
        const int r0 = wpx + mt * 16 + (lane >> 2);
        #pragma unroll
        for (int nt = 0; nt < 4; ++nt) {
            const int n0 = nt * 8 + (lane & 3) * 2;
            ssim[n0 * SSIM_STRIDE + r0]           = d[mt][nt][0];
            ssim[(n0 + 1) * SSIM_STRIDE + r0]     = d[mt][nt][1];
            ssim[n0 * SSIM_STRIDE + r0 + 8]       = d[mt][nt][2];
            ssim[(n0 + 1) * SSIM_STRIDE + r0 + 8] = d[mt][nt][3];
        }
    }
    // quad-reduce ssr over lanes sharing the same rows (lane&3 = 0..3)
    #pragma unroll
    for (int mt = 0; mt < 2; ++mt)
        #pragma unroll
        for (int j = 0; j < 2; ++j) {
            float v = ssr[mt][j];
            v += __shfl_xor_sync(0xffffffffu, v, 1);
            v += __shfl_xor_sync(0xffffffffu, v, 2);
            if ((lane & 3) == 0)
                sss[wpx + mt * 16 + j * 8 + (lane >> 2)] = v;
        }
    __syncthreads();

    const float inv = 1.0f / fmaxf(sqrtf(sss[tid]), 1e-12f);
    float sims[NCL], m = -1e30f;
    #pragma unroll
    for (int n = 0; n < NCL; ++n) {
        sims[n] = ssim[n * SSIM_STRIDE + tid] * inv;
        m = fmaxf(m, sims[n]);
    }
    float se = 0.0f, ses = 0.0f;
    #pragma unroll
    for (int n = 0; n < NCL; ++n) {
        const float e = __expf(2.0f * (sims[n] - m));
        se += e; ses += e * sims[n];
        sims[n] = e;
    }
    const float r = 1.0f / se;

    if (probs != nullptr && valid) {
        float* op = probs + (size_t)b * NCL * HW + pix;
        #pragma unroll
        for (int n = 0; n < NCL; ++n) op[(size_t)n * HW] = sims[n] * r;
    }

    float c = valid ? (ses * r) : 0.0f;
    #pragma unroll
    for (int o = 16; o > 0; o >>= 1) c += __shfl_xor_sync(0xffffffffu, c, o);
    if (lane == 0) sred[warp] = c;
    __syncthreads();
    if (tid == 0)
        atomicAdd(&g_accum, (double)(sred[0] + sred[1] + sred[2] + sred[3]));
}

// ---------------- Kernel C: finalize ----------------
__global__ void finalize_kernel(float* __restrict__ loss) {
    *loss = (float)(-g_accum / (double)TOTPX);
}

extern "C" void kernel_launch(void* const* d_in, const int* in_sizes, int n_in,
                              void* d_out, int out_size) {
    const float* x        = (const float*)d_in[0];
    const float* clusters = (const float*)d_in[1];
    float* out = (float*)d_out;

    float* probs_ptr = nullptr;
    float* loss_ptr  = nullptr;
    if (out_size >= PROBS_ELEMS) {
        probs_ptr = out + (out_size - PROBS_ELEMS);
        if (out_size > PROBS_ELEMS) loss_ptr = out;
    } else {
        loss_ptr = out;
    }

    normalize_clusters<<<NCL + 1, 256>>>(clusters);
    cluster_main<<<BATCH * TILES_PER_B, TPB>>>(x, probs_ptr);
    if (loss_ptr) finalize_kernel<<<1, 1>>>(loss_ptr);
}

// round 8
// speedup vs baseline: 3.5315x; 1.3230x over previous
#include <cuda_runtime.h>
#include <cstdint>

// ---------------- problem constants ----------------
#define BATCH   32
#define CH      512
#define HW      3136
#define NCL     27
#define TOTPX   (BATCH * HW)
#define PROBS_ELEMS (BATCH * NCL * HW)

#define MTILE   128                 // pixels per tile
#define TILES_PER_B 25              // ceil(3136/128), last tile 64 valid
#define NTILES  (BATCH * TILES_PER_B)   // 800
#define TPB     128
#define TILES_PER_CTA 2
#define CCH     8                   // channels per chunk (K step)
#define NCHUNKS (CH / CCH)          // 64
#define NPADN   32                  // clusters padded to 32 (rows 27-31 zero)

// ---------------- smem: 5-stage cp.async ring + separate epilogue ----------------
#define XS_STRIDE  136                              // floats, conflict-free frags
#define XSTG_BYTES (CCH * XS_STRIDE * 4)            // 4352 (x raw)
#define SB_STRIDE  12
#define BSTG_BYTES (NPADN * SB_STRIDE * 4)          // 1536 (B hi only)
#define STG_BYTES  (XSTG_BYTES + BSTG_BYTES)        // 5888
#define STAGES     5
#define RING_BYTES (STAGES * STG_BYTES)             // 29440
#define SSIM_STRIDE 132
#define EPI_BYTES  (NPADN * SSIM_STRIDE * 4 + MTILE * 4)   // 17408
#define SMEM_BYTES (RING_BYTES + EPI_BYTES)                // 46848 (< 48K static)

// ---------------- device scratch ----------------
__device__ float  g_nhi[NPADN * CH];   // rna(tf32) normalized clusters, pad rows zero
__device__ double g_accum;

// ---------------- helpers ----------------
__device__ __forceinline__ float tf32_rna(float x) {
    uint32_t u;
    asm("cvt.rna.tf32.f32 %0, %1;" : "=r"(u) : "f"(x));
    return __uint_as_float(u);
}
__device__ __forceinline__ void mma_tf32(float* d, const uint32_t* a, const uint32_t* b) {
    asm volatile(
        "mma.sync.aligned.m16n8k8.row.col.f32.tf32.tf32.f32 "
        "{%0,%1,%2,%3}, {%4,%5,%6,%7}, {%8,%9}, {%0,%1,%2,%3};"
        : "+f"(d[0]), "+f"(d[1]), "+f"(d[2]), "+f"(d[3])
        : "r"(a[0]), "r"(a[1]), "r"(a[2]), "r"(a[3]), "r"(b[0]), "r"(b[1]));
}
__device__ __forceinline__ void cp16(uint32_t dst, const void* src, int nbytes) {
    asm volatile("cp.async.cg.shared.global [%0], [%1], 16, %2;"
                 :: "r"(dst), "l"(src), "r"(nbytes) : "memory");
}
#define CP_COMMIT()  asm volatile("cp.async.commit_group;" ::: "memory")
#define CP_WAIT3()   asm volatile("cp.async.wait_group 3;" ::: "memory")

// ---------------- Kernel A: normalize clusters, rna-rounded ----------------
__global__ void normalize_clusters(const float* __restrict__ clusters) {
    __shared__ float swarp[8];
    const int n = blockIdx.x;
    const int tid = threadIdx.x, lane = tid & 31, w = tid >> 5;
    if (n >= NCL) {       // pad block: zero rows 27-31, reset accumulator
        for (int i = tid; i < (NPADN - NCL) * CH; i += 256) g_nhi[NCL * CH + i] = 0.0f;
        if (tid == 0) g_accum = 0.0;
        return;
    }
    const float* row = clusters + (size_t)n * CH;
    float ss = 0.0f;
    for (int c = tid; c < CH; c += 256) { float v = row[c]; ss += v * v; }
    #pragma unroll
    for (int o = 16; o > 0; o >>= 1) ss += __shfl_xor_sync(0xffffffffu, ss, o);
    if (lane == 0) swarp[w] = ss;
    __syncthreads();
    if (tid == 0) {
        float t = 0.0f;
        #pragma unroll
        for (int i = 0; i < 8; ++i) t += swarp[i];
        swarp[0] = t;
    }
    __syncthreads();
    const float inv = 1.0f / fmaxf(sqrtf(swarp[0]), 1e-12f);
    for (int c = tid; c < CH; c += 256)
        g_nhi[n * CH + c] = tf32_rna(row[c] * inv);
}

// ---------------- Kernel B: main tf32 HMMA (rna), cp.async pipelined, 2 tiles ----------------
__global__ void __launch_bounds__(TPB, 4)
cluster_main(const float* __restrict__ x, float* __restrict__ probs) {
    __shared__ __align__(16) char sm[SMEM_BYTES];
    __shared__ float sred[4];

    const int tid  = threadIdx.x;
    const int lane = tid & 31;
    const int warp = tid >> 5;
    const uint32_t smb = (uint32_t)__cvta_generic_to_shared(sm);
    const int wpx = warp * 32;

    // B staging: threads 0-63, one 16B transfer (hi plane only)
    const int brow  = (tid & 63) >> 1;
    const int bhalf = tid & 1;
    const float* bsrc_base = g_nhi + (size_t)brow * CH + bhalf * 4;
    const bool do_b = (tid < 64);

    float* ssim = (float*)(sm + RING_BYTES);             // [32][132]
    float* sss  = (float*)(sm + RING_BYTES + NPADN * SSIM_STRIDE * 4);  // [128]

    for (int seg = 0; seg < TILES_PER_CTA; ++seg) {
        const int g    = blockIdx.x * TILES_PER_CTA + seg;
        const int b    = g / TILES_PER_B;
        const int tile = g % TILES_PER_B;
        const int pix  = tile * MTILE + tid;
        const bool valid = (pix < HW);
        const float* xtile = x + (size_t)b * CH * HW + tile * MTILE;

        const bool seg_ok = (tile * MTILE + lane * 4 + 4 <= HW);
        const int xbytes = seg_ok ? 16 : 0;

        auto issue_stage = [&](int chunk) {
            const uint32_t base = smb + (uint32_t)(chunk % STAGES) * STG_BYTES;
            const float* s0 = xtile + (size_t)(chunk * CCH + warp) * HW + lane * 4;
            const float* s1 = s0 + (size_t)4 * HW;
            cp16(base + (uint32_t)warp * (XS_STRIDE * 4) + lane * 16,
                 seg_ok ? (const void*)s0 : (const void*)xtile, xbytes);
            cp16(base + (uint32_t)(warp + 4) * (XS_STRIDE * 4) + lane * 16,
                 seg_ok ? (const void*)s1 : (const void*)xtile, xbytes);
            if (do_b)
                cp16(base + XSTG_BYTES + brow * (SB_STRIDE * 4) + bhalf * 16,
                     bsrc_base + chunk * CCH, 16);
        };

        float d[2][4][4];
        #pragma unroll
        for (int mt = 0; mt < 2; ++mt)
            #pragma unroll
            for (int nt = 0; nt < 4; ++nt)
                #pragma unroll
                for (int i = 0; i < 4; ++i) d[mt][nt][i] = 0.0f;
        float ssr[2][2] = {{0.f, 0.f}, {0.f, 0.f}};

        issue_stage(0); CP_COMMIT();
        issue_stage(1); CP_COMMIT();
        issue_stage(2); CP_COMMIT();

        for (int kc = 0; kc < NCHUNKS; ++kc) {
            if (kc + 3 < NCHUNKS) issue_stage(kc + 3);
            CP_COMMIT();
            CP_WAIT3();
            __syncthreads();

            const char* stg  = sm + (kc % STAGES) * STG_BYTES;
            const float* xs  = (const float*)stg;
            const float* sBh = (const float*)(stg + XSTG_BYTES);

            uint32_t ah[2][4], bh[4][2];
            #pragma unroll
            for (int mt = 0; mt < 2; ++mt) {
                const int base = (lane & 3) * XS_STRIDE + wpx + mt * 16 + (lane >> 2);
                const float r0 = xs[base];
                const float r1 = xs[base + 8];
                const float r2 = xs[base + 4 * XS_STRIDE];
                const float r3 = xs[base + 4 * XS_STRIDE + 8];
                ssr[mt][0] = fmaf(r0, r0, fmaf(r2, r2, ssr[mt][0]));
                ssr[mt][1] = fmaf(r1, r1, fmaf(r3, r3, ssr[mt][1]));
                ah[mt][0] = __float_as_uint(tf32_rna(r0));
                ah[mt][1] = __float_as_uint(tf32_rna(r1));
                ah[mt][2] = __float_as_uint(tf32_rna(r2));
                ah[mt][3] = __float_as_uint(tf32_rna(r3));
            }
            #pragma unroll
            for (int nt = 0; nt < 4; ++nt) {
                const int bb = (nt * 8 + (lane >> 2)) * SB_STRIDE + (lane & 3);
                bh[nt][0] = __float_as_uint(sBh[bb]);
                bh[nt][1] = __float_as_uint(sBh[bb + 4]);
            }
            #pragma unroll
            for (int mt = 0; mt < 2; ++mt)
                #pragma unroll
                for (int nt = 0; nt < 4; ++nt)
                    mma_tf32(d[mt][nt], ah[mt], bh[nt]);
            __syncthreads();
        }

        // ---- epilogue (separate smem region) ----
        #pragma unroll
        for (int mt = 0; mt < 2; ++mt) {
            const int r0 = wpx + mt * 16 + (lane >> 2);
            #pragma unroll
            for (int nt = 0; nt < 4; ++nt) {
                const int n0 = nt * 8 + (lane & 3) * 2;
                ssim[n0 * SSIM_STRIDE + r0]           = d[mt][nt][0];
                ssim[(n0 + 1) * SSIM_STRIDE + r0]     = d[mt][nt][1];
                ssim[n0 * SSIM_STRIDE + r0 + 8]       = d[mt][nt][2];
                ssim[(n0 + 1) * SSIM_STRIDE + r0 + 8] = d[mt][nt][3];
            }
        }
        #pragma unroll
        for (int mt = 0; mt < 2; ++mt)
            #pragma unroll
            for (int j = 0; j < 2; ++j) {
                float vv = ssr[mt][j];
                vv += __shfl_xor_sync(0xffffffffu, vv, 1);
                vv += __shfl_xor_sync(0xffffffffu, vv, 2);
                if ((lane & 3) == 0)
                    sss[wpx + mt * 16 + j * 8 + (lane >> 2)] = vv;
            }
        __syncthreads();

        const float inv = 1.0f / fmaxf(sqrtf(sss[tid]), 1e-12f);
        float sims[NCL], m = -1e30f;
        #pragma unroll
        for (int n = 0; n < NCL; ++n) {
            sims[n] = ssim[n * SSIM_STRIDE + tid] * inv;
            m = fmaxf(m, sims[n]);
        }
        float se = 0.0f, ses = 0.0f;
        #pragma unroll
        for (int n = 0; n < NCL; ++n) {
            const float e = __expf(2.0f * (sims[n] - m));
            se += e; ses += e * sims[n];
            sims[n] = e;
        }
        const float r = 1.0f / se;

        if (probs != nullptr && valid) {
            float* op = probs + (size_t)b * NCL * HW + pix;
            #pragma unroll
            for (int n = 0; n < NCL; ++n) op[(size_t)n * HW] = sims[n] * r;
        }

        float c = valid ? (ses * r) : 0.0f;
        #pragma unroll
        for (int o = 16; o > 0; o >>= 1) c += __shfl_xor_sync(0xffffffffu, c, o);
        if (lane == 0) sred[warp] = c;
        __syncthreads();
        if (tid == 0)
            atomicAdd(&g_accum, (double)(sred[0] + sred[1] + sred[2] + sred[3]));
        __syncthreads();   // sred/epilogue smem safe before next tile
    }
}

// ---------------- Kernel C: finalize ----------------
__global__ void finalize_kernel(float* __restrict__ loss) {
    *loss = (float)(-g_accum / (double)TOTPX);
}

extern "C" void kernel_launch(void* const* d_in, const int* in_sizes, int n_in,
                              void* d_out, int out_size) {
    const float* x        = (const float*)d_in[0];
    const float* clusters = (const float*)d_in[1];
    float* out = (float*)d_out;

    float* probs_ptr = nullptr;
    float* loss_ptr  = nullptr;
    if (out_size >= PROBS_ELEMS) {
        probs_ptr = out + (out_size - PROBS_ELEMS);
        if (out_size > PROBS_ELEMS) loss_ptr = out;
    } else {
        loss_ptr = out;
    }

    normalize_clusters<<<NCL + 1, 256>>>(clusters);
    cluster_main<<<NTILES / TILES_PER_CTA, TPB>>>(x, probs_ptr);
    if (loss_ptr) finalize_kernel<<<1, 1>>>(loss_ptr);
}